// round 6
// baseline (speedup 1.0000x reference)
#include <cuda_runtime.h>

#define W 224
#define WW (W * W)                  // 50176
#define F4_PER (WW / 4)             // 12544 float4 per sample
#define F4_PER_ROW (W / 4)          // 56
#define NSAMP 256
#define BLK_PER_SAMP 7
#define NBLK1 (NSAMP * BLK_PER_SAMP)        // 1792
#define F4_PER_BLK (F4_PER / BLK_PER_SAMP)  // 1792 = 256 thr * 7 f4
#define NBLK2 NBLK1
#define LN2 0.6931471805599453

// Scratch (device globals; zero-init at load; g_acc/g_cnt reset by last block)
__device__ int4     g_blk[NBLK1];   // per-block {maxbits, cnt, si, sj}
__device__ double   g_acc;
__device__ unsigned g_cnt;

__device__ __forceinline__ float fast_lg2(float x) {
    float r; asm("lg2.approx.f32 %0, %1;" : "=f"(r) : "f"(x)); return r;
}
__device__ __forceinline__ float fast_sqrt(float x) {
    float r; asm("sqrt.approx.f32 %0, %1;" : "=f"(r) : "f"(x)); return r;
}
__device__ __forceinline__ float fast_rcp(float x) {
    float r; asm("rcp.approx.f32 %0, %1;" : "=f"(r) : "f"(x)); return r;
}

// ---------------------------------------------------------------------------
// Kernel 1: per-block max + tie stats in ONE pass (ties counted from registers).
// grid = 1792 (7 blocks/sample), 256 threads, 7 float4 per thread.
// ---------------------------------------------------------------------------
__global__ __launch_bounds__(256) void k_maxstats(const float* __restrict__ tgt) {
    const int b = blockIdx.x / BLK_PER_SAMP;
    const int c = blockIdx.x - b * BLK_PER_SAMP;
    const int tid = threadIdx.x;
    const float4* __restrict__ t4 =
        reinterpret_cast<const float4*>(tgt) + (size_t)b * F4_PER + c * F4_PER_BLK;

    float4 v[7];
    #pragma unroll
    for (int k = 0; k < 7; k++) v[k] = t4[k * 256 + tid];

    float tmax = -3.0e38f;
    #pragma unroll
    for (int k = 0; k < 7; k++)
        tmax = fmaxf(tmax, fmaxf(fmaxf(v[k].x, v[k].y), fmaxf(v[k].z, v[k].w)));

    float m = tmax;
    #pragma unroll
    for (int o = 16; o > 0; o >>= 1)
        m = fmaxf(m, __shfl_xor_sync(0xffffffffu, m, o));

    __shared__ float smax[8];
    __shared__ float sM;
    __shared__ int scnt, ssi, ssj;
    const int wid = tid >> 5, lid = tid & 31;
    if (lid == 0) smax[wid] = m;
    if (tid == 0) { scnt = 0; ssi = 0; ssj = 0; }
    __syncthreads();
    if (tid == 0) {
        float bm = smax[0];
        #pragma unroll
        for (int w = 1; w < 8; w++) bm = fmaxf(bm, smax[w]);
        sM = bm;
    }
    __syncthreads();
    const float M = sM;

    if (tmax == M) {   // rare: only threads holding the block max
        int cnt = 0, si = 0, sj = 0;
        #pragma unroll
        for (int k = 0; k < 7; k++) {
            const int r4 = c * F4_PER_BLK + k * 256 + tid;
            const int i  = r4 / F4_PER_ROW;
            const int j0 = (r4 - i * F4_PER_ROW) * 4;
            if (v[k].x == M) { cnt++; si += i; sj += j0;     }
            if (v[k].y == M) { cnt++; si += i; sj += j0 + 1; }
            if (v[k].z == M) { cnt++; si += i; sj += j0 + 2; }
            if (v[k].w == M) { cnt++; si += i; sj += j0 + 3; }
        }
        atomicAdd_block(&scnt, cnt);
        atomicAdd_block(&ssi,  si);
        atomicAdd_block(&ssj,  sj);
    }
    __syncthreads();

    if (tid == 0) {
        const unsigned mb = __float_as_uint(M);   // target >= 0 -> bit order == float order
        g_blk[blockIdx.x] = make_int4((int)mb, scnt, ssi, ssj);
    }
}

// ---------------------------------------------------------------------------
// Kernel 2: weighted BCE, lean inner loop. grid = (7, 256): y=sample, x=chunk.
// Accumulates sum of rcp(sqrt(d2)+1) * bce_log2; constants W*ln2/N folded into
// the finalize multiplier. Last block writes out[0] and resets accumulators.
// ---------------------------------------------------------------------------
__global__ __launch_bounds__(256) void k_loss(const float* __restrict__ inp,
                                              const float* __restrict__ tgt,
                                              float* __restrict__ out,
                                              double scale) {
    const int samp = blockIdx.y;
    const int c    = blockIdx.x;
    const int tid  = threadIdx.x;

    __shared__ float2 sxy;
    if (tid == 0) {
        int4 e[BLK_PER_SAMP];
        #pragma unroll
        for (int q = 0; q < BLK_PER_SAMP; q++) e[q] = g_blk[samp * BLK_PER_SAMP + q];
        unsigned mb = 0u;
        #pragma unroll
        for (int q = 0; q < BLK_PER_SAMP; q++) mb = max(mb, (unsigned)e[q].x);
        int cnt = 0, si = 0, sj = 0;
        #pragma unroll
        for (int q = 0; q < BLK_PER_SAMP; q++)
            if ((unsigned)e[q].x == mb) { cnt += e[q].y; si += e[q].z; sj += e[q].w; }
        const float inv = 1.0f / (float)cnt;
        sxy = make_float2((float)si * inv, (float)sj * inv);
    }
    __syncthreads();
    const float cx = sxy.x, cy = sxy.y;

    const size_t base = (size_t)samp * F4_PER + c * F4_PER_BLK;
    const float4* __restrict__ p4 = reinterpret_cast<const float4*>(inp) + base;
    const float4* __restrict__ t4 = reinterpret_cast<const float4*>(tgt) + base;

    float s = 0.0f;

    // software pipeline: loads for k+1 in flight while processing k
    float4 pv = p4[tid];
    float4 tv = t4[tid];
    #pragma unroll
    for (int k = 0; k < 7; k++) {
        float4 pn, tn;
        if (k < 6) {
            pn = p4[(k + 1) * 256 + tid];
            tn = t4[(k + 1) * 256 + tid];
        }

        const int r4 = c * F4_PER_BLK + k * 256 + tid;   // f4 idx within sample
        const int i  = r4 / F4_PER_ROW;
        const int j0 = (r4 - i * F4_PER_ROW) * 4;
        const float di  = (float)i - cx;
        const float di2 = di * di;
        const float dj0 = (float)j0 - cy;

        float pe[4] = {pv.x, pv.y, pv.z, pv.w};
        float te[4] = {tv.x, tv.y, tv.z, tv.w};
        #pragma unroll
        for (int e = 0; e < 4; e++) {
            // weight (sans W): 1/(sqrt(d2)+1)
            float dj  = dj0 + (float)e;
            float d2  = fmaf(dj, dj, di2);
            float wr  = fast_rcp(fast_sqrt(d2) + 1.0f);
            // bce in log2 units: -(t*lp2 + (1-t)*lq2) = t*(lq2-lp2) - lq2
            float lp2 = fast_lg2(pe[e]);
            float lq2 = fast_lg2(1.0f - pe[e]);
            float bce = fmaf(te[e], lq2 - lp2, -lq2);
            s = fmaf(wr, bce, s);
        }
        pv = pn; tv = tn;
    }

    #pragma unroll
    for (int o = 16; o > 0; o >>= 1)
        s += __shfl_xor_sync(0xffffffffu, s, o);

    __shared__ float sw[8];
    const int wid = tid >> 5, lid = tid & 31;
    if (lid == 0) sw[wid] = s;
    __syncthreads();
    if (tid == 0) {
        float bs = sw[0];
        #pragma unroll
        for (int w = 1; w < 8; w++) bs += sw[w];
        atomicAdd(&g_acc, (double)bs);
        __threadfence();
        const unsigned ticket = atomicAdd(&g_cnt, 1u);
        if (ticket == NBLK2 - 1) {          // last block: finalize + reset
            const double total = atomicAdd(&g_acc, 0.0);
            out[0] = (float)(total * scale);
            g_acc = 0.0;
            g_cnt = 0u;
        }
    }
}

extern "C" void kernel_launch(void* const* d_in, const int* in_sizes, int n_in,
                              void* d_out, int out_size) {
    const float* inp = (const float*)d_in[0];
    const float* tgt = (const float*)d_in[1];
    float* out = (float*)d_out;

    k_maxstats<<<NBLK1, 256>>>(tgt);
    dim3 g2(BLK_PER_SAMP, NSAMP);
    // scale = W * ln2 / N   (W from weight numerator, ln2 from log2->ln, 1/N mean)
    const double scale = (double)W * LN2 / (double)((size_t)NSAMP * WW);
    k_loss<<<g2, 256>>>(inp, tgt, out, scale);
}